// round 5
// baseline (speedup 1.0000x reference)
#include <cuda_runtime.h>
#include <math.h>

// x[1, 2M, 16] fp32, ~5% NaN. Per-column mean of valid entries; NaNs -> mean.
//
// Single persistent kernel:
//   phase1: stream tile once: raw copy x -> out (evict-first stores),
//           per-column sum/count in registers, single 64-bit "any NaN in
//           this float4" mask per thread.
//   grid barrier
//   phase2: for flagged iterations only, reload float4 from in, replace
//           NaN components with column mean, store fixed float4.

#define C 16
#define THREADS 256

struct Acc {
    float sum[C];
    float cnt[C];
    unsigned int counter;
};
__device__ Acc g_acc;

__global__ void __launch_bounds__(THREADS)
fused_kernel(const float4* __restrict__ in, float4* __restrict__ out,
             long long n4, long long chunk) {
    __shared__ float s_sum[C];
    __shared__ float s_cnt[C];
    __shared__ float s_mean[C];

    const int t = threadIdx.x;
    if (t < C) { s_sum[t] = 0.0f; s_cnt[t] = 0.0f; }
    __syncthreads();

    const long long base  = (long long)blockIdx.x * chunk;
    const long long end   = (base + chunk < n4) ? (base + chunk) : n4;
    const long long start = base + t;

    const int cg    = (int)(start & 3);   // loop-invariant column group
    const int cbase = cg * 4;

    float ls0 = 0.f, ls1 = 0.f, ls2 = 0.f, ls3 = 0.f;
    float lc0 = 0.f, lc1 = 0.f, lc2 = 0.f, lc3 = 0.f;
    unsigned long long anymask = 0ull;
    unsigned long long bit = 1ull;

    // ---------- phase 1: single streaming pass ----------
    #pragma unroll 4
    for (long long i = start; i < end; i += THREADS) {
        float4 v = in[i];
        bool v0 = (v.x == v.x);
        bool v1 = (v.y == v.y);
        bool v2 = (v.z == v.z);
        bool v3 = (v.w == v.w);
        if (v0) { ls0 += v.x; lc0 += 1.f; }
        if (v1) { ls1 += v.y; lc1 += 1.f; }
        if (v2) { ls2 += v.z; lc2 += 1.f; }
        if (v3) { ls3 += v.w; lc3 += 1.f; }
        if (!(v0 && v1 && v2 && v3)) anymask |= bit;
        bit <<= 1;
        __stcs(&out[i], v);   // raw copy-through, evict-first
    }

    atomicAdd(&s_sum[cbase + 0], ls0);
    atomicAdd(&s_sum[cbase + 1], ls1);
    atomicAdd(&s_sum[cbase + 2], ls2);
    atomicAdd(&s_sum[cbase + 3], ls3);
    atomicAdd(&s_cnt[cbase + 0], lc0);
    atomicAdd(&s_cnt[cbase + 1], lc1);
    atomicAdd(&s_cnt[cbase + 2], lc2);
    atomicAdd(&s_cnt[cbase + 3], lc3);
    __syncthreads();

    if (t < C) {
        atomicAdd(&g_acc.sum[t], s_sum[t]);
        atomicAdd(&g_acc.cnt[t], s_cnt[t]);
        __threadfence();
    }
    __syncthreads();

    // ---------- grid barrier ----------
    if (t == 0) {
        atomicAdd(&g_acc.counter, 1u);
        volatile unsigned int* ctr = &g_acc.counter;
        while (*ctr < gridDim.x) {
            __nanosleep(64);
        }
        __threadfence();
    }
    __syncthreads();

    if (t < C) {
        s_mean[t] = g_acc.sum[t] / fmaxf(g_acc.cnt[t], 1.0f);
    }
    __syncthreads();

    // ---------- phase 2: fix flagged float4s only ----------
    if (anymask) {
        const float mu0 = s_mean[cbase + 0];
        const float mu1 = s_mean[cbase + 1];
        const float mu2 = s_mean[cbase + 2];
        const float mu3 = s_mean[cbase + 3];
        unsigned long long m = anymask;
        while (m) {
            int k = __ffsll((long long)m) - 1;
            m &= m - 1ull;
            long long i = start + (long long)k * THREADS;
            float4 v = in[i];
            if (!(v.x == v.x)) v.x = mu0;
            if (!(v.y == v.y)) v.y = mu1;
            if (!(v.z == v.z)) v.z = mu2;
            if (!(v.w == v.w)) v.w = mu3;
            out[i] = v;
        }
    }
}

extern "C" void kernel_launch(void* const* d_in, const int* in_sizes, int n_in,
                              void* d_out, int out_size) {
    const float4* in = (const float4*)d_in[0];
    float4* out      = (float4*)d_out;
    long long n  = (long long)in_sizes[0];
    long long n4 = n / 4;

    static int grid = 0;
    static void* acc_ptr = nullptr;
    if (grid == 0) {
        int sm_count = 0;
        cudaDeviceGetAttribute(&sm_count, cudaDevAttrMultiProcessorCount, 0);
        int blocks_per_sm = 0;
        cudaOccupancyMaxActiveBlocksPerMultiprocessor(
            &blocks_per_sm, fused_kernel, THREADS, 0);
        if (blocks_per_sm < 1) blocks_per_sm = 1;
        grid = sm_count * blocks_per_sm;
        // 64-bit mask limit: iterations per thread must be <= 64.
        long long min_grid = (n4 + 64LL * THREADS - 1) / (64LL * THREADS);
        if (grid < min_grid) grid = (int)min_grid;
        cudaGetSymbolAddress(&acc_ptr, g_acc);
    }

    long long chunk = (n4 + grid - 1) / grid;

    cudaMemsetAsync(acc_ptr, 0, sizeof(Acc));
    fused_kernel<<<grid, THREADS>>>(in, out, n4, chunk);
}

// round 7
// speedup vs baseline: 1.5594x; 1.5594x over previous
#include <cuda_runtime.h>
#include <math.h>

// x[1, 2M, 16] fp32, ~5% NaN. Per-column mean of valid entries; NaNs -> mean.
// R3 structure (uniform two-phase streaming, software grid barrier) +
// L2-retention hints: phase-2 stores are evict-first (__stcs) so the output
// stream does not evict the input lines phase 1 just cached; phase-2 reads
// use __ldcs (consume-once). Phase 2 walks the tile in reverse order.

#define C 16
#define THREADS 256

struct Acc {
    float sum[C];
    float cnt[C];
    unsigned int counter;
};
__device__ Acc g_acc;

__global__ void __launch_bounds__(THREADS)
fused_kernel(const float4* __restrict__ in, float4* __restrict__ out,
             long long n4, long long chunk) {
    __shared__ float s_sum[C];
    __shared__ float s_cnt[C];
    __shared__ float s_mean[C];

    const int t = threadIdx.x;
    if (t < C) { s_sum[t] = 0.0f; s_cnt[t] = 0.0f; }
    __syncthreads();

    const long long base  = (long long)blockIdx.x * chunk;
    const long long end   = (base + chunk < n4) ? (base + chunk) : n4;
    const long long start = base + t;

    const int cg    = (int)(start & 3);   // loop-invariant column group
    const int cbase = cg * 4;

    float ls0 = 0.f, ls1 = 0.f, ls2 = 0.f, ls3 = 0.f;
    float lc0 = 0.f, lc1 = 0.f, lc2 = 0.f, lc3 = 0.f;

    // ---------- phase 1: reduce own tile (reads populate L2) ----------
    #pragma unroll 4
    for (long long i = start; i < end; i += THREADS) {
        float4 v = in[i];
        if (v.x == v.x) { ls0 += v.x; lc0 += 1.f; }
        if (v.y == v.y) { ls1 += v.y; lc1 += 1.f; }
        if (v.z == v.z) { ls2 += v.z; lc2 += 1.f; }
        if (v.w == v.w) { ls3 += v.w; lc3 += 1.f; }
    }

    atomicAdd(&s_sum[cbase + 0], ls0);
    atomicAdd(&s_sum[cbase + 1], ls1);
    atomicAdd(&s_sum[cbase + 2], ls2);
    atomicAdd(&s_sum[cbase + 3], ls3);
    atomicAdd(&s_cnt[cbase + 0], lc0);
    atomicAdd(&s_cnt[cbase + 1], lc1);
    atomicAdd(&s_cnt[cbase + 2], lc2);
    atomicAdd(&s_cnt[cbase + 3], lc3);
    __syncthreads();

    if (t < C) {
        atomicAdd(&g_acc.sum[t], s_sum[t]);
        atomicAdd(&g_acc.cnt[t], s_cnt[t]);
        __threadfence();
    }
    __syncthreads();

    // ---------- grid barrier ----------
    if (t == 0) {
        atomicAdd(&g_acc.counter, 1u);
        volatile unsigned int* ctr = &g_acc.counter;
        while (*ctr < gridDim.x) {
            __nanosleep(64);
        }
        __threadfence();
    }
    __syncthreads();

    if (t < C) {
        s_mean[t] = g_acc.sum[t] / fmaxf(g_acc.cnt[t], 1.0f);
    }
    __syncthreads();

    const float m0 = s_mean[cbase + 0];
    const float m1 = s_mean[cbase + 1];
    const float m2 = s_mean[cbase + 2];
    const float m3 = s_mean[cbase + 3];

    // ---------- phase 2: reverse-order fill (L2-hot input first) ----------
    if (start < end) {
        long long K = (end - start + THREADS - 1) / THREADS;  // iterations
        #pragma unroll 4
        for (long long k = K - 1; k >= 0; k--) {
            long long i = start + k * THREADS;
            float4 v = __ldcs(&in[i]);           // consume-once read
            if (!(v.x == v.x)) v.x = m0;
            if (!(v.y == v.y)) v.y = m1;
            if (!(v.z == v.z)) v.z = m2;
            if (!(v.w == v.w)) v.w = m3;
            __stcs(&out[i], v);                  // evict-first store
        }
    }
}

extern "C" void kernel_launch(void* const* d_in, const int* in_sizes, int n_in,
                              void* d_out, int out_size) {
    const float4* in = (const float4*)d_in[0];
    float4* out      = (float4*)d_out;
    long long n  = (long long)in_sizes[0];
    long long n4 = n / 4;

    static int grid = 0;
    static void* acc_ptr = nullptr;
    if (grid == 0) {
        int sm_count = 0;
        cudaDeviceGetAttribute(&sm_count, cudaDevAttrMultiProcessorCount, 0);
        int blocks_per_sm = 0;
        cudaOccupancyMaxActiveBlocksPerMultiprocessor(
            &blocks_per_sm, fused_kernel, THREADS, 0);
        if (blocks_per_sm < 1) blocks_per_sm = 1;
        grid = sm_count * blocks_per_sm;
        cudaGetSymbolAddress(&acc_ptr, g_acc);
    }

    long long chunk = (n4 + grid - 1) / grid;

    cudaMemsetAsync(acc_ptr, 0, sizeof(Acc));
    fused_kernel<<<grid, THREADS>>>(in, out, n4, chunk);
}